// round 7
// baseline (speedup 1.0000x reference)
#include <cuda_runtime.h>
#include <cstdint>

#define NODES   16384
#define NPG     128
#define NG      128
#define HID     128
#define KNN     24
#define SXT_S   132

typedef unsigned long long u64;

// ---------------- scratch ----------------
__device__ float g_feat_a[NODES * HID];
__device__ float g_feat_b[NODES * HID];
__device__ float g_pq[NODES * 2 * HID];
__device__ float g_wc3[3 * HID * 2 * HID];
__device__ int   g_lists[NODES * KNN];

__device__ __forceinline__ float elu_fast(float v) {
    return v > 0.0f ? v : (__expf(v) - 1.0f);
}

__device__ __forceinline__ unsigned fkey(float v) {
    unsigned b = __float_as_uint(v);
    return b ^ ((b & 0x80000000u) ? 0xffffffffu : 0x80000000u);
}

// ---- packed fp32x2 helpers (sm_103a FFMA2) ----
__device__ __forceinline__ u64 pack2(float lo, float hi) {
    u64 r; asm("mov.b64 %0,{%1,%2};" : "=l"(r) : "f"(lo), "f"(hi)); return r;
}
__device__ __forceinline__ void unpack2(u64 v, float& lo, float& hi) {
    asm("mov.b64 {%0,%1},%2;" : "=f"(lo), "=f"(hi) : "l"(v));
}
__device__ __forceinline__ void dfma(u64& d, u64 a, u64 b) {
    asm("fma.rn.f32x2 %0,%1,%2,%0;" : "+l"(d) : "l"(a), "l"(b));
}

// ---- cp.async helpers ----
__device__ __forceinline__ void cp16(void* smem, const void* gmem) {
    unsigned s = (unsigned)__cvta_generic_to_shared(smem);
    asm volatile("cp.async.cg.shared.global [%0], [%1], 16;\n" :: "r"(s), "l"(gmem));
}
__device__ __forceinline__ void cp_commit() { asm volatile("cp.async.commit_group;\n"); }
__device__ __forceinline__ void cp_wait0()  { asm volatile("cp.async.wait_group 0;\n"); }

// ---------------- R5 mm body (FFMA2, pipelined), smem passed in -----------
// As: 2*16*132 floats, Bs: 2*16*128 floats.
__device__ __forceinline__ void mm_body(
    const float* __restrict__ A, const float* __restrict__ B,
    const float* __restrict__ bias, int biasLimit, int doElu,
    float* __restrict__ C, int N, int K, int rowBase, int colBase,
    float* As, float* Bs)
{
    const int tid = threadIdx.x;
    const int tx = tid & 15;
    const int ty = tid >> 4;

    u64 acc2[4][8];
#pragma unroll
    for (int r = 0; r < 4; r++)
#pragma unroll
        for (int c = 0; c < 8; c++) acc2[r][c] = 0ull;

    int am[8], ak[8];
#pragma unroll
    for (int t = 0; t < 8; t++) {
        int idx = t * 256 + tid;
        am[t] = idx >> 4; ak[t] = idx & 15;
    }
    int bk[2], bn[2];
#pragma unroll
    for (int t = 0; t < 2; t++) {
        int idx = t * 256 + tid;
        bk[t] = idx >> 5;
        bn[t] = (idx & 31) * 4;
    }

    float aReg[8];
#pragma unroll
    for (int t = 0; t < 8; t++)
        aReg[t] = A[(size_t)(rowBase + am[t]) * K + ak[t]];
#pragma unroll
    for (int t = 0; t < 2; t++)
        cp16(&Bs[bk[t] * 128 + bn[t]], &B[(size_t)bk[t] * N + colBase + bn[t]]);
    cp_commit();
#pragma unroll
    for (int t = 0; t < 8; t++)
        As[ak[t] * 132 + am[t]] = aReg[t];
    cp_wait0();
    __syncthreads();

    int buf = 0;
    for (int kk = 0; kk < K; kk += 16) {
        const int nkk = kk + 16;
        if (nkk < K) {
#pragma unroll
            for (int t = 0; t < 8; t++)
                aReg[t] = A[(size_t)(rowBase + am[t]) * K + nkk + ak[t]];
#pragma unroll
            for (int t = 0; t < 2; t++)
                cp16(&Bs[(buf ^ 1) * 2048 + bk[t] * 128 + bn[t]],
                     &B[(size_t)(nkk + bk[t]) * N + colBase + bn[t]]);
            cp_commit();
        }

        const float* Asb = As + buf * 2112;
        const float* Bsb = Bs + buf * 2048;
#pragma unroll
        for (int k = 0; k < 16; k++) {
            const float* ap = &Asb[k * 132 + ty * 8];
            ulonglong2 t0 = *(const ulonglong2*)(ap);
            ulonglong2 t1 = *(const ulonglong2*)(ap + 4);
            u64 a[4] = {t0.x, t0.y, t1.x, t1.y};
            float4 b0 = *(const float4*)&Bsb[k * 128 + tx * 8];
            float4 b1 = *(const float4*)&Bsb[k * 128 + tx * 8 + 4];
            u64 bd[8];
            bd[0] = pack2(b0.x, b0.x); bd[1] = pack2(b0.y, b0.y);
            bd[2] = pack2(b0.z, b0.z); bd[3] = pack2(b0.w, b0.w);
            bd[4] = pack2(b1.x, b1.x); bd[5] = pack2(b1.y, b1.y);
            bd[6] = pack2(b1.z, b1.z); bd[7] = pack2(b1.w, b1.w);
#pragma unroll
            for (int r = 0; r < 4; r++)
#pragma unroll
                for (int c = 0; c < 8; c++) dfma(acc2[r][c], a[r], bd[c]);
        }

        if (nkk < K) {
#pragma unroll
            for (int t = 0; t < 8; t++)
                As[(buf ^ 1) * 2112 + ak[t] * 132 + am[t]] = aReg[t];
            cp_wait0();
            __syncthreads();
            buf ^= 1;
        }
    }

#pragma unroll
    for (int r = 0; r < 4; r++) {
        int row0 = rowBase + ty * 8 + 2 * r;
        float lo[8], hi[8];
#pragma unroll
        for (int c = 0; c < 8; c++) unpack2(acc2[r][c], lo[c], hi[c]);
#pragma unroll
        for (int c = 0; c < 8; c++) {
            int col = colBase + tx * 8 + c;
            if (col < biasLimit) { float bb = bias[col]; lo[c] += bb; hi[c] += bb; }
            if (doElu) { lo[c] = elu_fast(lo[c]); hi[c] = elu_fast(hi[c]); }
        }
        float* p0 = C + (size_t)row0 * N + colBase + tx * 8;
        float* p1 = p0 + N;
        *(float4*)p0       = make_float4(lo[0], lo[1], lo[2], lo[3]);
        *(float4*)(p0 + 4) = make_float4(lo[4], lo[5], lo[6], lo[7]);
        *(float4*)p1       = make_float4(hi[0], hi[1], hi[2], hi[3]);
        *(float4*)(p1 + 4) = make_float4(hi[4], hi[5], hi[6], hi[7]);
    }
}

#define MM_SMEM ((2*16*132 + 2*16*128) * 4)

// standalone matmul (encoder)
__global__ __launch_bounds__(256, 2) void mm_kernel(
    const float* __restrict__ A, const float* __restrict__ B,
    const float* __restrict__ bias, int biasLimit, int doElu,
    float* __restrict__ C, int N, int K)
{
    extern __shared__ float smf[];
    mm_body(A, B, bias, biasLimit, doElu, C, N, K,
            blockIdx.x * 128, blockIdx.y * 128, smf, smf + 2 * 16 * 132);
}

// ---------------- sel body: per-graph kNN select -> neighbor lists ---------
// 256 threads. smem: sXT 128*132 + sSq 128 floats.
__device__ void sel_body(const float* __restrict__ X, int* __restrict__ lists,
                         int g, float* smf)
{
    float* sXT = smf;
    float* sSq = smf + 128 * SXT_S;
    const int tid = threadIdx.x;
    const float* Xg = X + (size_t)g * NPG * HID;

    for (int idx = tid; idx < NPG * HID; idx += 256) {
        int n = idx >> 7, f = idx & 127;
        sXT[f * SXT_S + n] = Xg[idx];
    }
    __syncthreads();

    if (tid < 128) {
        float s = 0.0f;
#pragma unroll 8
        for (int d = 0; d < 128; d++) {
            float v = sXT[d * SXT_S + tid];
            s += v * v;
        }
        sSq[tid] = s;
    }
    __syncthreads();

    const int w = tid >> 5;     // 0..7, owns 16 rows
    const int l = tid & 31;     // owns cols 4l..4l+3
    const int i0 = w * 16, j0 = l * 4;

    // Gram: acc2[r][c] = f32x2 over row-pair (i0+2r, i0+2r+1), col j0+c
    u64 acc2[8][4];
#pragma unroll
    for (int r = 0; r < 8; r++)
#pragma unroll
        for (int c = 0; c < 4; c++) acc2[r][c] = 0ull;

#pragma unroll 2
    for (int d = 0; d < 128; d++) {
        const float* rowp = sXT + d * SXT_S;
        const u64* ap = (const u64*)(rowp + i0);
        ulonglong2 a01 = *(const ulonglong2*)(ap);
        ulonglong2 a23 = *(const ulonglong2*)(ap + 2);
        ulonglong2 a45 = *(const ulonglong2*)(ap + 4);
        ulonglong2 a67 = *(const ulonglong2*)(ap + 6);
        u64 a[8] = {a01.x, a01.y, a23.x, a23.y, a45.x, a45.y, a67.x, a67.y};
        float4 bj = *(const float4*)(rowp + j0);
        u64 bd[4];
        bd[0] = pack2(bj.x, bj.x); bd[1] = pack2(bj.y, bj.y);
        bd[2] = pack2(bj.z, bj.z); bd[3] = pack2(bj.w, bj.w);
#pragma unroll
        for (int r = 0; r < 8; r++)
#pragma unroll
            for (int c = 0; c < 4; c++) dfma(acc2[r][c], a[r], bd[c]);
    }

    // convert to packed keys: acc2[r][c] := (key_hi<<32)|key_lo
    float sqj[4];
#pragma unroll
    for (int c = 0; c < 4; c++) sqj[c] = sSq[j0 + c];
#pragma unroll
    for (int r = 0; r < 8; r++) {
        int ia = i0 + 2 * r;
        float sqa = sSq[ia], sqb = sSq[ia + 1];
#pragma unroll
        for (int c = 0; c < 4; c++) {
            float lo, hi;
            unpack2(acc2[r][c], lo, hi);
            unsigned kl = fkey(sqa + sqj[c] - 2.0f * lo);
            unsigned kh = fkey(sqb + sqj[c] - 2.0f * hi);
            acc2[r][c] = ((u64)kh << 32) | (u64)kl;
        }
    }

    const unsigned lmask = (1u << l) - 1u;

#pragma unroll 1
    for (int r = 0; r < 8; r++) {
        unsigned ka[2][4];
#pragma unroll
        for (int c = 0; c < 4; c++) {
            ka[0][c] = (unsigned)acc2[r][c];
            ka[1][c] = (unsigned)(acc2[r][c] >> 32);
        }

        // dual binary search for 24th-smallest key
        unsigned lo0 = 0, hi0 = 0xffffffffu, lo1 = 0, hi1 = 0xffffffffu;
#pragma unroll 1
        for (int it = 0; it < 32; it++) {
            unsigned m0 = lo0 + ((hi0 - lo0) >> 1);
            unsigned m1 = lo1 + ((hi1 - lo1) >> 1);
            int c0 = (ka[0][0] <= m0) + (ka[0][1] <= m0) + (ka[0][2] <= m0) + (ka[0][3] <= m0);
            int c1 = (ka[1][0] <= m1) + (ka[1][1] <= m1) + (ka[1][2] <= m1) + (ka[1][3] <= m1);
            c0 = __reduce_add_sync(0xffffffffu, c0);
            c1 = __reduce_add_sync(0xffffffffu, c1);
            if (c0 >= KNN) hi0 = m0; else lo0 = m0 + 1;
            if (c1 >= KNN) hi1 = m1; else lo1 = m1 + 1;
        }
        const unsigned KV[2] = {lo0, lo1};

#pragma unroll 1
        for (int rr = 0; rr < 2; rr++) {
            const int i = i0 + 2 * r + rr;
            const unsigned kv = KV[rr];

            int cl = 0;
#pragma unroll
            for (int c = 0; c < 4; c++) cl += (ka[rr][c] < kv) ? 1 : 0;
            int c0tot = __reduce_add_sync(0xffffffffu, cl);
            int rem = KNN - c0tot;   // ties to take in ascending j (j = 4l+c)

            bool eq[4], sel[4];
            unsigned bal[4];
#pragma unroll
            for (int c = 0; c < 4; c++) {
                eq[c] = (ka[rr][c] == kv);
                bal[c] = __ballot_sync(0xffffffffu, eq[c]);
            }
            int tiesLower = 0;
#pragma unroll
            for (int c = 0; c < 4; c++) tiesLower += __popc(bal[c] & lmask);
            int lp = 0;
#pragma unroll
            for (int c = 0; c < 4; c++) {
                sel[c] = (ka[rr][c] < kv) || (eq[c] && (tiesLower + lp) < rem);
                lp += eq[c] ? 1 : 0;
            }

            unsigned sbal[4];
#pragma unroll
            for (int c = 0; c < 4; c++) sbal[c] = __ballot_sync(0xffffffffu, sel[c]);
            int selLower = 0;
#pragma unroll
            for (int c = 0; c < 4; c++) selLower += __popc(sbal[c] & lmask);
            int sp = 0;
#pragma unroll
            for (int c = 0; c < 4; c++) {
                if (sel[c])
                    lists[((size_t)g * NPG + i) * KNN + selLower + sp] = j0 + c;
                sp += sel[c] ? 1 : 0;
            }
        }
    }
}

#define SEL_SMEM ((128 * SXT_S + 128) * 4)
#define FUSED_SMEM (SEL_SMEM > MM_SMEM ? SEL_SMEM : MM_SMEM)

// ---------------- fused: 256 mm CTAs + 128 sel CTAs, interleaved -----------
__global__ __launch_bounds__(256, 2) void conv_fused(
    const float* __restrict__ cur, const float* __restrict__ wc,
    const float* __restrict__ bias, float* __restrict__ pq,
    int* __restrict__ lists)
{
    extern __shared__ float smf[];
    const int bid = blockIdx.x;        // 0..383
    const int t3 = bid / 3, r3 = bid - 3 * t3;
    if (r3 < 2) {
        const int mi = t3 * 2 + r3;    // 0..255
        mm_body(cur, wc, bias, 128, 0, pq, 2 * HID, HID,
                (mi & 127) * 128, (mi >> 7) * 128, smf, smf + 2 * 16 * 132);
    } else {
        sel_body(cur, lists, t3, smf);
    }
}

// ---------------- aggregate: lists + pq -> out -----------------------------
#define AGG_SMEM ((128 * 128 + 128 * KNN) * 4)

__global__ __launch_bounds__(512, 1) void agg_kernel(
    const float* __restrict__ PQ, const int* __restrict__ lists,
    float* __restrict__ OUT)
{
    extern __shared__ float smf[];
    float* sQ = smf;                        // [n][f] 128x128
    int*   sL = (int*)(smf + 128 * 128);    // [i][24]

    const int g   = blockIdx.x;
    const int tid = threadIdx.x;
    const float* PQg = PQ + (size_t)g * NPG * 2 * HID;
    const int*   Lg  = lists + (size_t)g * NPG * KNN;

    // async q tile: 4096 16B chunks, 8/thread
#pragma unroll
    for (int t = 0; t < 8; t++) {
        int idx = t * 512 + tid;
        int n = idx >> 5, c4 = (idx & 31) * 4;
        cp16(&sQ[n * 128 + c4], &PQg[n * 256 + 128 + c4]);
    }
    cp_commit();

    for (int idx = tid; idx < NPG * KNN; idx += 512) sL[idx] = Lg[idx];
    cp_wait0();
    __syncthreads();

    const int w = tid >> 5;   // 16 warps, 8 rows each
    const int l = tid & 31;
    const int fo = 4 * l;

    for (int rr = 0; rr < 8; rr++) {
        const int i = w * 8 + rr;
        float4 pv = *(const float4*)(PQg + (size_t)i * 256 + fo);
        float4 qm = make_float4(-3.0e38f, -3.0e38f, -3.0e38f, -3.0e38f);
#pragma unroll 4
        for (int it = 0; it < KNN; it++) {
            int j = sL[i * KNN + it];
            float4 qv = *(const float4*)(sQ + j * 128 + fo);
            qm.x = fmaxf(qm.x, qv.x);
            qm.y = fmaxf(qm.y, qv.y);
            qm.z = fmaxf(qm.z, qv.z);
            qm.w = fmaxf(qm.w, qv.w);
        }
        float4 ov;
        ov.x = elu_fast(pv.x + qm.x);
        ov.y = elu_fast(pv.y + qm.y);
        ov.z = elu_fast(pv.z + qm.z);
        ov.w = elu_fast(pv.w + qm.w);
        *(float4*)(OUT + ((size_t)g * NPG + i) * HID + fo) = ov;
    }
}

// ---------------- build [Wa-Wb | Wb] ---------------------------------------
__global__ void build_wcat(const float* __restrict__ w, float* __restrict__ wc)
{
    int idx = blockIdx.x * 256 + threadIdx.x;
    int d = idx >> 8;
    int n = idx & 255;
    float v;
    if (n < 128) v = w[d * 128 + n] - w[(128 + d) * 128 + n];
    else         v = w[(128 + d) * 128 + (n - 128)];
    wc[idx] = v;
}

// ---------------- sum-pool + output MLP -------------------------------------
__global__ __launch_bounds__(128) void pool_mlp(
    const float* __restrict__ X,
    const float* __restrict__ w1, const float* __restrict__ b1,
    const float* __restrict__ w2, const float* __restrict__ b2,
    const float* __restrict__ w3, const float* __restrict__ b3,
    const float* __restrict__ w4, const float* __restrict__ b4,
    float* __restrict__ out)
{
    __shared__ float pooled[128];
    __shared__ float o1[64];
    __shared__ float o2[32];
    __shared__ float o3[32];
    const int g = blockIdx.x, t = threadIdx.x;
    const float* Xg = X + (size_t)g * NPG * HID;

    float s = 0.0f;
    for (int n = 0; n < NPG; n++) s += Xg[n * HID + t];
    pooled[t] = s;
    __syncthreads();

    if (t < 64) {
        float a = b1[t];
        for (int d = 0; d < 128; d++) a += pooled[d] * w1[d * 64 + t];
        o1[t] = elu_fast(a);
    }
    __syncthreads();
    if (t < 32) {
        float a = b2[t];
        for (int d = 0; d < 64; d++) a += o1[d] * w2[d * 32 + t];
        o2[t] = elu_fast(a);
    }
    __syncthreads();
    if (t < 32) {
        float a = b3[t];
        for (int d = 0; d < 32; d++) a += o2[d] * w3[d * 32 + t];
        o3[t] = elu_fast(a);
    }
    __syncthreads();
    if (t < 6) {
        float a = b4[t];
        for (int d = 0; d < 32; d++) a += o3[d] * w4[d * 6 + t];
        out[g * 6 + t] = a;
    }
}

__global__ void copy_batch(const int* __restrict__ b, float* __restrict__ out)
{
    int i = blockIdx.x * 256 + threadIdx.x;
    if (i < NODES) out[i] = (float)b[i];
}

// ---------------------------------------------------------------------------
extern "C" void kernel_launch(void* const* d_in, const int* in_sizes, int n_in,
                              void* d_out, int out_size)
{
    const float* x_pf    = (const float*)d_in[0];
    const float* enc_w1  = (const float*)d_in[1];
    const float* enc_b1  = (const float*)d_in[2];
    const float* enc_w2  = (const float*)d_in[3];
    const float* enc_b2  = (const float*)d_in[4];
    const float* conv_w[3] = {(const float*)d_in[5], (const float*)d_in[7], (const float*)d_in[9]};
    const float* conv_b[3] = {(const float*)d_in[6], (const float*)d_in[8], (const float*)d_in[10]};
    const float* out_w1  = (const float*)d_in[11];
    const float* out_b1  = (const float*)d_in[12];
    const float* out_w2  = (const float*)d_in[13];
    const float* out_b2  = (const float*)d_in[14];
    const float* out_w3  = (const float*)d_in[15];
    const float* out_b3  = (const float*)d_in[16];
    const float* out_w4  = (const float*)d_in[17];
    const float* out_b4  = (const float*)d_in[18];
    const int*   batch   = (const int*)d_in[19];

    float *featA, *featB, *pq, *wc3;
    int* lists;
    cudaGetSymbolAddress((void**)&featA, g_feat_a);
    cudaGetSymbolAddress((void**)&featB, g_feat_b);
    cudaGetSymbolAddress((void**)&pq,    g_pq);
    cudaGetSymbolAddress((void**)&wc3,   g_wc3);
    cudaGetSymbolAddress((void**)&lists, g_lists);

    cudaFuncSetAttribute(mm_kernel,  cudaFuncAttributeMaxDynamicSharedMemorySize, MM_SMEM);
    cudaFuncSetAttribute(conv_fused, cudaFuncAttributeMaxDynamicSharedMemorySize, FUSED_SMEM);
    cudaFuncSetAttribute(agg_kernel, cudaFuncAttributeMaxDynamicSharedMemorySize, AGG_SMEM);

    // weight concat for all 3 convs (independent of activations)
    for (int c = 0; c < 3; c++)
        build_wcat<<<128, 256>>>(conv_w[c], wc3 + c * HID * 2 * HID);

    // encoder
    mm_kernel<<<dim3(NODES / 128, 1), 256, MM_SMEM>>>(x_pf,  enc_w1, enc_b1, 128, 1, featB, 128, 16);
    mm_kernel<<<dim3(NODES / 128, 1), 256, MM_SMEM>>>(featB, enc_w2, enc_b2, 128, 1, featA, 128, 128);

    // 3 dynamic edge convs: fused (pq matmul || knn-select), then aggregate
    float* cur = featA;
    float* nxt = featB;
    for (int cidx = 0; cidx < 3; cidx++) {
        conv_fused<<<384, 256, FUSED_SMEM>>>(cur, wc3 + cidx * HID * 2 * HID,
                                             conv_b[cidx], pq, lists);
        agg_kernel<<<NG, 512, AGG_SMEM>>>(pq, lists, nxt);
        float* t = cur; cur = nxt; nxt = t;
    }

    pool_mlp<<<NG, 128>>>(cur, out_w1, out_b1, out_w2, out_b2,
                          out_w3, out_b3, out_w4, out_b4, (float*)d_out);

    copy_batch<<<(NODES + 255) / 256, 256>>>(batch, (float*)d_out + NG * 6);
}

// round 8
// speedup vs baseline: 1.0690x; 1.0690x over previous
#include <cuda_runtime.h>
#include <cstdint>

#define NODES   16384
#define NPG     128
#define NG      128
#define HID     128
#define KNN     24
#define SXT_S   132

typedef unsigned long long u64;

// ---------------- scratch ----------------
__device__ float g_feat_a[NODES * HID];
__device__ float g_feat_b[NODES * HID];
__device__ float g_pq[NODES * 2 * HID];
__device__ float g_wc3[3 * HID * 2 * HID];
__device__ int   g_lists[NODES * KNN];

__device__ __forceinline__ float elu_fast(float v) {
    return v > 0.0f ? v : (__expf(v) - 1.0f);
}

__device__ __forceinline__ unsigned fkey(float v) {
    unsigned b = __float_as_uint(v);
    return b ^ ((b & 0x80000000u) ? 0xffffffffu : 0x80000000u);
}

// ---- packed fp32x2 helpers (sm_103a FFMA2) ----
__device__ __forceinline__ u64 pack2(float lo, float hi) {
    u64 r; asm("mov.b64 %0,{%1,%2};" : "=l"(r) : "f"(lo), "f"(hi)); return r;
}
__device__ __forceinline__ void unpack2(u64 v, float& lo, float& hi) {
    asm("mov.b64 {%0,%1},%2;" : "=f"(lo), "=f"(hi) : "l"(v));
}
__device__ __forceinline__ void dfma(u64& d, u64 a, u64 b) {
    asm("fma.rn.f32x2 %0,%1,%2,%0;" : "+l"(d) : "l"(a), "l"(b));
}

// ---- cp.async helpers ----
__device__ __forceinline__ void cp16(void* smem, const void* gmem) {
    unsigned s = (unsigned)__cvta_generic_to_shared(smem);
    asm volatile("cp.async.cg.shared.global [%0], [%1], 16;\n" :: "r"(s), "l"(gmem));
}
__device__ __forceinline__ void cp_commit() { asm volatile("cp.async.commit_group;\n"); }
__device__ __forceinline__ void cp_wait0()  { asm volatile("cp.async.wait_group 0;\n"); }

// ---------------- R5 mm body (FFMA2, pipelined), smem passed in -----------
__device__ __forceinline__ void mm_body(
    const float* __restrict__ A, const float* __restrict__ B,
    const float* __restrict__ bias, int biasLimit, int doElu,
    float* __restrict__ C, int N, int K, int rowBase, int colBase,
    float* As, float* Bs)
{
    const int tid = threadIdx.x;
    const int tx = tid & 15;
    const int ty = tid >> 4;

    u64 acc2[4][8];
#pragma unroll
    for (int r = 0; r < 4; r++)
#pragma unroll
        for (int c = 0; c < 8; c++) acc2[r][c] = 0ull;

    int am[8], ak[8];
#pragma unroll
    for (int t = 0; t < 8; t++) {
        int idx = t * 256 + tid;
        am[t] = idx >> 4; ak[t] = idx & 15;
    }
    int bk[2], bn[2];
#pragma unroll
    for (int t = 0; t < 2; t++) {
        int idx = t * 256 + tid;
        bk[t] = idx >> 5;
        bn[t] = (idx & 31) * 4;
    }

    float aReg[8];
#pragma unroll
    for (int t = 0; t < 8; t++)
        aReg[t] = A[(size_t)(rowBase + am[t]) * K + ak[t]];
#pragma unroll
    for (int t = 0; t < 2; t++)
        cp16(&Bs[bk[t] * 128 + bn[t]], &B[(size_t)bk[t] * N + colBase + bn[t]]);
    cp_commit();
#pragma unroll
    for (int t = 0; t < 8; t++)
        As[ak[t] * 132 + am[t]] = aReg[t];
    cp_wait0();
    __syncthreads();

    int buf = 0;
    for (int kk = 0; kk < K; kk += 16) {
        const int nkk = kk + 16;
        if (nkk < K) {
#pragma unroll
            for (int t = 0; t < 8; t++)
                aReg[t] = A[(size_t)(rowBase + am[t]) * K + nkk + ak[t]];
#pragma unroll
            for (int t = 0; t < 2; t++)
                cp16(&Bs[(buf ^ 1) * 2048 + bk[t] * 128 + bn[t]],
                     &B[(size_t)(nkk + bk[t]) * N + colBase + bn[t]]);
            cp_commit();
        }

        const float* Asb = As + buf * 2112;
        const float* Bsb = Bs + buf * 2048;
#pragma unroll
        for (int k = 0; k < 16; k++) {
            const float* ap = &Asb[k * 132 + ty * 8];
            ulonglong2 t0 = *(const ulonglong2*)(ap);
            ulonglong2 t1 = *(const ulonglong2*)(ap + 4);
            u64 a[4] = {t0.x, t0.y, t1.x, t1.y};
            float4 b0 = *(const float4*)&Bsb[k * 128 + tx * 8];
            float4 b1 = *(const float4*)&Bsb[k * 128 + tx * 8 + 4];
            u64 bd[8];
            bd[0] = pack2(b0.x, b0.x); bd[1] = pack2(b0.y, b0.y);
            bd[2] = pack2(b0.z, b0.z); bd[3] = pack2(b0.w, b0.w);
            bd[4] = pack2(b1.x, b1.x); bd[5] = pack2(b1.y, b1.y);
            bd[6] = pack2(b1.z, b1.z); bd[7] = pack2(b1.w, b1.w);
#pragma unroll
            for (int r = 0; r < 4; r++)
#pragma unroll
                for (int c = 0; c < 8; c++) dfma(acc2[r][c], a[r], bd[c]);
        }

        if (nkk < K) {
#pragma unroll
            for (int t = 0; t < 8; t++)
                As[(buf ^ 1) * 2112 + ak[t] * 132 + am[t]] = aReg[t];
            cp_wait0();
            __syncthreads();
            buf ^= 1;
        }
    }

#pragma unroll
    for (int r = 0; r < 4; r++) {
        int row0 = rowBase + ty * 8 + 2 * r;
        float lo[8], hi[8];
#pragma unroll
        for (int c = 0; c < 8; c++) unpack2(acc2[r][c], lo[c], hi[c]);
#pragma unroll
        for (int c = 0; c < 8; c++) {
            int col = colBase + tx * 8 + c;
            if (col < biasLimit) { float bb = bias[col]; lo[c] += bb; hi[c] += bb; }
            if (doElu) { lo[c] = elu_fast(lo[c]); hi[c] = elu_fast(hi[c]); }
        }
        float* p0 = C + (size_t)row0 * N + colBase + tx * 8;
        float* p1 = p0 + N;
        *(float4*)p0       = make_float4(lo[0], lo[1], lo[2], lo[3]);
        *(float4*)(p0 + 4) = make_float4(lo[4], lo[5], lo[6], lo[7]);
        *(float4*)p1       = make_float4(hi[0], hi[1], hi[2], hi[3]);
        *(float4*)(p1 + 4) = make_float4(hi[4], hi[5], hi[6], hi[7]);
    }
}

#define MM_SMEM ((2*16*132 + 2*16*128) * 4)

// standalone matmul (encoder)
__global__ __launch_bounds__(256, 2) void mm_kernel(
    const float* __restrict__ A, const float* __restrict__ B,
    const float* __restrict__ bias, int biasLimit, int doElu,
    float* __restrict__ C, int N, int K)
{
    extern __shared__ float smf[];
    mm_body(A, B, bias, biasLimit, doElu, C, N, K,
            blockIdx.x * 128, blockIdx.y * 128, smf, smf + 2 * 16 * 132);
}

// ---------------- sel body: per-graph kNN select -> neighbor lists ---------
// 256 threads. smem: sXT 128*132 + sSq 128 floats.  (verified in R7)
__device__ void sel_body(const float* __restrict__ X, int* __restrict__ lists,
                         int g, float* smf)
{
    float* sXT = smf;
    float* sSq = smf + 128 * SXT_S;
    const int tid = threadIdx.x;
    const float* Xg = X + (size_t)g * NPG * HID;

    for (int idx = tid; idx < NPG * HID; idx += 256) {
        int n = idx >> 7, f = idx & 127;
        sXT[f * SXT_S + n] = Xg[idx];
    }
    __syncthreads();

    if (tid < 128) {
        float s = 0.0f;
#pragma unroll 8
        for (int d = 0; d < 128; d++) {
            float v = sXT[d * SXT_S + tid];
            s += v * v;
        }
        sSq[tid] = s;
    }
    __syncthreads();

    const int w = tid >> 5;
    const int l = tid & 31;
    const int i0 = w * 16, j0 = l * 4;

    u64 acc2[8][4];
#pragma unroll
    for (int r = 0; r < 8; r++)
#pragma unroll
        for (int c = 0; c < 4; c++) acc2[r][c] = 0ull;

#pragma unroll 2
    for (int d = 0; d < 128; d++) {
        const float* rowp = sXT + d * SXT_S;
        const u64* ap = (const u64*)(rowp + i0);
        ulonglong2 a01 = *(const ulonglong2*)(ap);
        ulonglong2 a23 = *(const ulonglong2*)(ap + 2);
        ulonglong2 a45 = *(const ulonglong2*)(ap + 4);
        ulonglong2 a67 = *(const ulonglong2*)(ap + 6);
        u64 a[8] = {a01.x, a01.y, a23.x, a23.y, a45.x, a45.y, a67.x, a67.y};
        float4 bj = *(const float4*)(rowp + j0);
        u64 bd[4];
        bd[0] = pack2(bj.x, bj.x); bd[1] = pack2(bj.y, bj.y);
        bd[2] = pack2(bj.z, bj.z); bd[3] = pack2(bj.w, bj.w);
#pragma unroll
        for (int r = 0; r < 8; r++)
#pragma unroll
            for (int c = 0; c < 4; c++) dfma(acc2[r][c], a[r], bd[c]);
    }

    float sqj[4];
#pragma unroll
    for (int c = 0; c < 4; c++) sqj[c] = sSq[j0 + c];
#pragma unroll
    for (int r = 0; r < 8; r++) {
        int ia = i0 + 2 * r;
        float sqa = sSq[ia], sqb = sSq[ia + 1];
#pragma unroll
        for (int c = 0; c < 4; c++) {
            float lo, hi;
            unpack2(acc2[r][c], lo, hi);
            unsigned kl = fkey(sqa + sqj[c] - 2.0f * lo);
            unsigned kh = fkey(sqb + sqj[c] - 2.0f * hi);
            acc2[r][c] = ((u64)kh << 32) | (u64)kl;
        }
    }

    const unsigned lmask = (1u << l) - 1u;

#pragma unroll 1
    for (int r = 0; r < 8; r++) {
        unsigned ka[2][4];
#pragma unroll
        for (int c = 0; c < 4; c++) {
            ka[0][c] = (unsigned)acc2[r][c];
            ka[1][c] = (unsigned)(acc2[r][c] >> 32);
        }

        unsigned lo0 = 0, hi0 = 0xffffffffu, lo1 = 0, hi1 = 0xffffffffu;
#pragma unroll 1
        for (int it = 0; it < 32; it++) {
            unsigned m0 = lo0 + ((hi0 - lo0) >> 1);
            unsigned m1 = lo1 + ((hi1 - lo1) >> 1);
            int c0 = (ka[0][0] <= m0) + (ka[0][1] <= m0) + (ka[0][2] <= m0) + (ka[0][3] <= m0);
            int c1 = (ka[1][0] <= m1) + (ka[1][1] <= m1) + (ka[1][2] <= m1) + (ka[1][3] <= m1);
            c0 = __reduce_add_sync(0xffffffffu, c0);
            c1 = __reduce_add_sync(0xffffffffu, c1);
            if (c0 >= KNN) hi0 = m0; else lo0 = m0 + 1;
            if (c1 >= KNN) hi1 = m1; else lo1 = m1 + 1;
        }
        const unsigned KV[2] = {lo0, lo1};

#pragma unroll 1
        for (int rr = 0; rr < 2; rr++) {
            const int i = i0 + 2 * r + rr;
            const unsigned kv = KV[rr];

            int cl = 0;
#pragma unroll
            for (int c = 0; c < 4; c++) cl += (ka[rr][c] < kv) ? 1 : 0;
            int c0tot = __reduce_add_sync(0xffffffffu, cl);
            int rem = KNN - c0tot;

            bool eq[4], sel[4];
            unsigned bal[4];
#pragma unroll
            for (int c = 0; c < 4; c++) {
                eq[c] = (ka[rr][c] == kv);
                bal[c] = __ballot_sync(0xffffffffu, eq[c]);
            }
            int tiesLower = 0;
#pragma unroll
            for (int c = 0; c < 4; c++) tiesLower += __popc(bal[c] & lmask);
            int lp = 0;
#pragma unroll
            for (int c = 0; c < 4; c++) {
                sel[c] = (ka[rr][c] < kv) || (eq[c] && (tiesLower + lp) < rem);
                lp += eq[c] ? 1 : 0;
            }

            unsigned sbal[4];
#pragma unroll
            for (int c = 0; c < 4; c++) sbal[c] = __ballot_sync(0xffffffffu, sel[c]);
            int selLower = 0;
#pragma unroll
            for (int c = 0; c < 4; c++) selLower += __popc(sbal[c] & lmask);
            int sp = 0;
#pragma unroll
            for (int c = 0; c < 4; c++) {
                if (sel[c])
                    lists[((size_t)g * NPG + i) * KNN + selLower + sp] = j0 + c;
                sp += sel[c] ? 1 : 0;
            }
        }
    }
}

#define SEL_SMEM ((128 * SXT_S + 128) * 4)
#define FUSED_SMEM (SEL_SMEM > MM_SMEM ? SEL_SMEM : MM_SMEM)

// ---------------- fused: 128 mm CTAs (2 tiles each) + 128 sel CTAs ---------
// 256 CTAs total -> ONE wave at 2 CTAs/SM.
__global__ __launch_bounds__(256, 2) void conv_fused(
    const float* __restrict__ cur, const float* __restrict__ wc,
    const float* __restrict__ bias, float* __restrict__ pq,
    int* __restrict__ lists)
{
    extern __shared__ float smf[];
    const int bid = blockIdx.x;        // 0..255
    const int half = bid >> 1;
    if ((bid & 1) == 0) {
        const int rowBase = half * 128;
        mm_body(cur, wc, bias, 128, 0, pq, 2 * HID, HID,
                rowBase, 0,   smf, smf + 2 * 16 * 132);
        __syncthreads();
        mm_body(cur, wc, bias, 128, 0, pq, 2 * HID, HID,
                rowBase, 128, smf, smf + 2 * 16 * 132);
    } else {
        sel_body(cur, lists, half, smf);
    }
}

// ---------------- aggregate: lists + pq -> out (verified in R7) ------------
#define AGG_SMEM ((128 * 128 + 128 * KNN) * 4)

__global__ __launch_bounds__(512, 1) void agg_kernel(
    const float* __restrict__ PQ, const int* __restrict__ lists,
    float* __restrict__ OUT)
{
    extern __shared__ float smf[];
    float* sQ = smf;
    int*   sL = (int*)(smf + 128 * 128);

    const int g   = blockIdx.x;
    const int tid = threadIdx.x;
    const float* PQg = PQ + (size_t)g * NPG * 2 * HID;
    const int*   Lg  = lists + (size_t)g * NPG * KNN;

#pragma unroll
    for (int t = 0; t < 8; t++) {
        int idx = t * 512 + tid;
        int n = idx >> 5, c4 = (idx & 31) * 4;
        cp16(&sQ[n * 128 + c4], &PQg[n * 256 + 128 + c4]);
    }
    cp_commit();

    for (int idx = tid; idx < NPG * KNN; idx += 512) sL[idx] = Lg[idx];
    cp_wait0();
    __syncthreads();

    const int w = tid >> 5;
    const int l = tid & 31;
    const int fo = 4 * l;

    for (int rr = 0; rr < 8; rr++) {
        const int i = w * 8 + rr;
        float4 pv = *(const float4*)(PQg + (size_t)i * 256 + fo);
        float4 qm = make_float4(-3.0e38f, -3.0e38f, -3.0e38f, -3.0e38f);
#pragma unroll 4
        for (int it = 0; it < KNN; it++) {
            int j = sL[i * KNN + it];
            float4 qv = *(const float4*)(sQ + j * 128 + fo);
            qm.x = fmaxf(qm.x, qv.x);
            qm.y = fmaxf(qm.y, qv.y);
            qm.z = fmaxf(qm.z, qv.z);
            qm.w = fmaxf(qm.w, qv.w);
        }
        float4 ov;
        ov.x = elu_fast(pv.x + qm.x);
        ov.y = elu_fast(pv.y + qm.y);
        ov.z = elu_fast(pv.z + qm.z);
        ov.w = elu_fast(pv.w + qm.w);
        *(float4*)(OUT + ((size_t)g * NPG + i) * HID + fo) = ov;
    }
}

// ---------------- build [Wa-Wb | Wb] ---------------------------------------
__global__ void build_wcat(const float* __restrict__ w, float* __restrict__ wc)
{
    int idx = blockIdx.x * 256 + threadIdx.x;
    int d = idx >> 8;
    int n = idx & 255;
    float v;
    if (n < 128) v = w[d * 128 + n] - w[(128 + d) * 128 + n];
    else         v = w[(128 + d) * 128 + (n - 128)];
    wc[idx] = v;
}

// ---------------- sum-pool + output MLP -------------------------------------
__global__ __launch_bounds__(128) void pool_mlp(
    const float* __restrict__ X,
    const float* __restrict__ w1, const float* __restrict__ b1,
    const float* __restrict__ w2, const float* __restrict__ b2,
    const float* __restrict__ w3, const float* __restrict__ b3,
    const float* __restrict__ w4, const float* __restrict__ b4,
    float* __restrict__ out)
{
    __shared__ float pooled[128];
    __shared__ float o1[64];
    __shared__ float o2[32];
    __shared__ float o3[32];
    const int g = blockIdx.x, t = threadIdx.x;
    const float* Xg = X + (size_t)g * NPG * HID;

    float s = 0.0f;
    for (int n = 0; n < NPG; n++) s += Xg[n * HID + t];
    pooled[t] = s;
    __syncthreads();

    if (t < 64) {
        float a = b1[t];
        for (int d = 0; d < 128; d++) a += pooled[d] * w1[d * 64 + t];
        o1[t] = elu_fast(a);
    }
    __syncthreads();
    if (t < 32) {
        float a = b2[t];
        for (int d = 0; d < 64; d++) a += o1[d] * w2[d * 32 + t];
        o2[t] = elu_fast(a);
    }
    __syncthreads();
    if (t < 32) {
        float a = b3[t];
        for (int d = 0; d < 32; d++) a += o2[d] * w3[d * 32 + t];
        o3[t] = elu_fast(a);
    }
    __syncthreads();
    if (t < 6) {
        float a = b4[t];
        for (int d = 0; d < 32; d++) a += o3[d] * w4[d * 6 + t];
        out[g * 6 + t] = a;
    }
}

__global__ void copy_batch(const int* __restrict__ b, float* __restrict__ out)
{
    int i = blockIdx.x * 256 + threadIdx.x;
    if (i < NODES) out[i] = (float)b[i];
}

// ---------------------------------------------------------------------------
extern "C" void kernel_launch(void* const* d_in, const int* in_sizes, int n_in,
                              void* d_out, int out_size)
{
    const float* x_pf    = (const float*)d_in[0];
    const float* enc_w1  = (const float*)d_in[1];
    const float* enc_b1  = (const float*)d_in[2];
    const float* enc_w2  = (const float*)d_in[3];
    const float* enc_b2  = (const float*)d_in[4];
    const float* conv_w[3] = {(const float*)d_in[5], (const float*)d_in[7], (const float*)d_in[9]};
    const float* conv_b[3] = {(const float*)d_in[6], (const float*)d_in[8], (const float*)d_in[10]};
    const float* out_w1  = (const float*)d_in[11];
    const float* out_b1  = (const float*)d_in[12];
    const float* out_w2  = (const float*)d_in[13];
    const float* out_b2  = (const float*)d_in[14];
    const float* out_w3  = (const float*)d_in[15];
    const float* out_b3  = (const float*)d_in[16];
    const float* out_w4  = (const float*)d_in[17];
    const float* out_b4  = (const float*)d_in[18];
    const int*   batch   = (const int*)d_in[19];

    float *featA, *featB, *pq, *wc3;
    int* lists;
    cudaGetSymbolAddress((void**)&featA, g_feat_a);
    cudaGetSymbolAddress((void**)&featB, g_feat_b);
    cudaGetSymbolAddress((void**)&pq,    g_pq);
    cudaGetSymbolAddress((void**)&wc3,   g_wc3);
    cudaGetSymbolAddress((void**)&lists, g_lists);

    cudaFuncSetAttribute(mm_kernel,  cudaFuncAttributeMaxDynamicSharedMemorySize, MM_SMEM);
    cudaFuncSetAttribute(conv_fused, cudaFuncAttributeMaxDynamicSharedMemorySize, FUSED_SMEM);
    cudaFuncSetAttribute(agg_kernel, cudaFuncAttributeMaxDynamicSharedMemorySize, AGG_SMEM);

    // weight concat for all 3 convs (independent of activations)
    for (int c = 0; c < 3; c++)
        build_wcat<<<128, 256>>>(conv_w[c], wc3 + c * HID * 2 * HID);

    // encoder
    mm_kernel<<<dim3(NODES / 128, 1), 256, MM_SMEM>>>(x_pf,  enc_w1, enc_b1, 128, 1, featB, 128, 16);
    mm_kernel<<<dim3(NODES / 128, 1), 256, MM_SMEM>>>(featB, enc_w2, enc_b2, 128, 1, featA, 128, 128);

    // 3 dynamic edge convs: fused (pq matmul || knn-select) in ONE wave, then aggregate
    float* cur = featA;
    float* nxt = featB;
    for (int cidx = 0; cidx < 3; cidx++) {
        conv_fused<<<256, 256, FUSED_SMEM>>>(cur, wc3 + cidx * HID * 2 * HID,
                                             conv_b[cidx], pq, lists);
        agg_kernel<<<NG, 512, AGG_SMEM>>>(pq, lists, nxt);
        float* t = cur; cur = nxt; nxt = t;
    }

    pool_mlp<<<NG, 128>>>(cur, out_w1, out_b1, out_w2, out_b2,
                          out_w3, out_b3, out_w4, out_b4, (float*)d_out);

    copy_batch<<<(NODES + 255) / 256, 256>>>(batch, (float*)d_out + NG * 6);
}

// round 9
// speedup vs baseline: 1.3373x; 1.2510x over previous
#include <cuda_runtime.h>
#include <cstdint>

#define NODES   16384
#define NPG     128
#define NG      128
#define HID     128
#define KNN     24
#define SXT_S   132

typedef unsigned long long u64;

// ---------------- scratch ----------------
__device__ float g_feat_a[NODES * HID];
__device__ float g_feat_b[NODES * HID];
__device__ float g_pq[NODES * 2 * HID];
__device__ float g_wc3[3 * HID * 2 * HID];

__device__ __forceinline__ float elu_fast(float v) {
    return v > 0.0f ? v : (__expf(v) - 1.0f);
}

__device__ __forceinline__ unsigned fkey(float v) {
    unsigned b = __float_as_uint(v);
    return b ^ ((b & 0x80000000u) ? 0xffffffffu : 0x80000000u);
}

// ---- packed fp32x2 helpers (sm_103a FFMA2) ----
__device__ __forceinline__ u64 pack2(float lo, float hi) {
    u64 r; asm("mov.b64 %0,{%1,%2};" : "=l"(r) : "f"(lo), "f"(hi)); return r;
}
__device__ __forceinline__ void unpack2(u64 v, float& lo, float& hi) {
    asm("mov.b64 {%0,%1},%2;" : "=f"(lo), "=f"(hi) : "l"(v));
}
__device__ __forceinline__ void dfma(u64& d, u64 a, u64 b) {
    asm("fma.rn.f32x2 %0,%1,%2,%0;" : "+l"(d) : "l"(a), "l"(b));
}

// ---- cp.async helpers ----
__device__ __forceinline__ void cp16(void* smem, const void* gmem) {
    unsigned s = (unsigned)__cvta_generic_to_shared(smem);
    asm volatile("cp.async.cg.shared.global [%0], [%1], 16;\n" :: "r"(s), "l"(gmem));
}
__device__ __forceinline__ void cp_commit() { asm volatile("cp.async.commit_group;\n"); }
__device__ __forceinline__ void cp_wait0()  { asm volatile("cp.async.wait_group 0;\n"); }

// ---------------- pipelined 128x128-tile fp32 matmul (FFMA2) ---------------
// (R5 code, verified: pq mm 31.4us, enc1 ~10us)
__global__ __launch_bounds__(256, 2) void mm_kernel(
    const float* __restrict__ A, const float* __restrict__ B,
    const float* __restrict__ bias, int biasLimit, int doElu,
    float* __restrict__ C, int N, int K)
{
    extern __shared__ float smf[];
    float* As = smf;                   // [2][16*132]
    float* Bs = smf + 2 * 16 * 132;    // [2][16*128]

    const int tid = threadIdx.x;
    const int tx = tid & 15;
    const int ty = tid >> 4;
    const int rowBase = blockIdx.x * 128;
    const int colBase = blockIdx.y * 128;

    u64 acc2[4][8];
#pragma unroll
    for (int r = 0; r < 4; r++)
#pragma unroll
        for (int c = 0; c < 8; c++) acc2[r][c] = 0ull;

    int am[8], ak[8];
#pragma unroll
    for (int t = 0; t < 8; t++) {
        int idx = t * 256 + tid;
        am[t] = idx >> 4; ak[t] = idx & 15;
    }
    int bk[2], bn[2];
#pragma unroll
    for (int t = 0; t < 2; t++) {
        int idx = t * 256 + tid;
        bk[t] = idx >> 5;
        bn[t] = (idx & 31) * 4;
    }

    float aReg[8];
#pragma unroll
    for (int t = 0; t < 8; t++)
        aReg[t] = A[(size_t)(rowBase + am[t]) * K + ak[t]];
#pragma unroll
    for (int t = 0; t < 2; t++)
        cp16(&Bs[bk[t] * 128 + bn[t]], &B[(size_t)bk[t] * N + colBase + bn[t]]);
    cp_commit();
#pragma unroll
    for (int t = 0; t < 8; t++)
        As[ak[t] * 132 + am[t]] = aReg[t];
    cp_wait0();
    __syncthreads();

    int buf = 0;
    for (int kk = 0; kk < K; kk += 16) {
        const int nkk = kk + 16;
        if (nkk < K) {
#pragma unroll
            for (int t = 0; t < 8; t++)
                aReg[t] = A[(size_t)(rowBase + am[t]) * K + nkk + ak[t]];
#pragma unroll
            for (int t = 0; t < 2; t++)
                cp16(&Bs[(buf ^ 1) * 2048 + bk[t] * 128 + bn[t]],
                     &B[(size_t)(nkk + bk[t]) * N + colBase + bn[t]]);
            cp_commit();
        }

        const float* Asb = As + buf * 2112;
        const float* Bsb = Bs + buf * 2048;
#pragma unroll
        for (int k = 0; k < 16; k++) {
            const float* ap = &Asb[k * 132 + ty * 8];
            ulonglong2 t0 = *(const ulonglong2*)(ap);
            ulonglong2 t1 = *(const ulonglong2*)(ap + 4);
            u64 a[4] = {t0.x, t0.y, t1.x, t1.y};
            float4 b0 = *(const float4*)&Bsb[k * 128 + tx * 8];
            float4 b1 = *(const float4*)&Bsb[k * 128 + tx * 8 + 4];
            u64 bd[8];
            bd[0] = pack2(b0.x, b0.x); bd[1] = pack2(b0.y, b0.y);
            bd[2] = pack2(b0.z, b0.z); bd[3] = pack2(b0.w, b0.w);
            bd[4] = pack2(b1.x, b1.x); bd[5] = pack2(b1.y, b1.y);
            bd[6] = pack2(b1.z, b1.z); bd[7] = pack2(b1.w, b1.w);
#pragma unroll
            for (int r = 0; r < 4; r++)
#pragma unroll
                for (int c = 0; c < 8; c++) dfma(acc2[r][c], a[r], bd[c]);
        }

        if (nkk < K) {
#pragma unroll
            for (int t = 0; t < 8; t++)
                As[(buf ^ 1) * 2112 + ak[t] * 132 + am[t]] = aReg[t];
            cp_wait0();
            __syncthreads();
            buf ^= 1;
        }
    }

#pragma unroll
    for (int r = 0; r < 4; r++) {
        int row0 = rowBase + ty * 8 + 2 * r;
        float lo[8], hi[8];
#pragma unroll
        for (int c = 0; c < 8; c++) unpack2(acc2[r][c], lo[c], hi[c]);
#pragma unroll
        for (int c = 0; c < 8; c++) {
            int col = colBase + tx * 8 + c;
            if (col < biasLimit) { float bb = bias[col]; lo[c] += bb; hi[c] += bb; }
            if (doElu) { lo[c] = elu_fast(lo[c]); hi[c] = elu_fast(hi[c]); }
        }
        float* p0 = C + (size_t)row0 * N + colBase + tx * 8;
        float* p1 = p0 + N;
        *(float4*)p0       = make_float4(lo[0], lo[1], lo[2], lo[3]);
        *(float4*)(p0 + 4) = make_float4(lo[4], lo[5], lo[6], lo[7]);
        *(float4*)p1       = make_float4(hi[0], hi[1], hi[2], hi[3]);
        *(float4*)(p1 + 4) = make_float4(hi[4], hi[5], hi[6], hi[7]);
    }
}

#define MM_SMEM ((2*16*132 + 2*16*128) * 4)

// ---------------- build [Wa-Wb | Wb] ---------------------------------------
__global__ void build_wcat(const float* __restrict__ w, float* __restrict__ wc)
{
    int idx = blockIdx.x * 256 + threadIdx.x;
    int d = idx >> 8;
    int n = idx & 255;
    float v;
    if (n < 128) v = w[d * 128 + n] - w[(128 + d) * 128 + n];
    else         v = w[(128 + d) * 128 + (n - 128)];
    wc[idx] = v;
}

// ---------------- fused per-graph kNN + select + aggregate -----------------
// 512 threads, 1 CTA/graph. Keys live in REGISTERS (no sD tile).
// smem: sXT 128*132 + sQ 128*128 + sSq 128 + sList 128*24(int)
#define SMEM_KNN ((128*SXT_S + 128*128 + 128 + 128*KNN) * 4)

__global__ __launch_bounds__(512, 1) void knn_agg(
    const float* __restrict__ X, const float* __restrict__ PQ,
    float* __restrict__ OUT)
{
    extern __shared__ float sm[];
    float* sXT = sm;                          // [f][n] stride 132
    float* sQ  = sXT + 128 * SXT_S;           // [n][f] 128x128
    float* sSq = sQ  + 128 * 128;             // [n]
    int*   sList = (int*)(sSq + 128);         // [i][24]

    const int g   = blockIdx.x;
    const int tid = threadIdx.x;
    const float* Xg  = X  + (size_t)g * NPG * HID;
    const float* PQg = PQ + (size_t)g * NPG * 2 * HID;

    // async copy of q tile (consumed only in aggregation)
#pragma unroll
    for (int t = 0; t < 8; t++) {
        int idx = t * 512 + tid;
        int n = idx >> 5, c4 = (idx & 31) * 4;
        cp16(&sQ[n * 128 + c4], &PQg[n * 256 + 128 + c4]);
    }
    cp_commit();

    // load X (transposed)
    for (int idx = tid; idx < NPG * HID; idx += 512) {
        int n = idx >> 7, f = idx & 127;
        sXT[f * SXT_S + n] = Xg[idx];
    }
    __syncthreads();

    // squared norms
    if (tid < 128) {
        float s = 0.0f;
#pragma unroll 8
        for (int d = 0; d < 128; d++) {
            float v = sXT[d * SXT_S + tid];
            s += v * v;
        }
        sSq[tid] = s;
    }
    __syncthreads();

    // Gram across all 16 warps: warp w owns rows w*8..w*8+7, lane l owns
    // cols 4l..4l+3. acc2[r][c] = f32x2 over row-pair (i0+2r, i0+2r+1).
    const int w = tid >> 5;
    const int l = tid & 31;
    const int i0 = w * 8, j0 = l * 4;

    u64 acc2[4][4];
#pragma unroll
    for (int r = 0; r < 4; r++)
#pragma unroll
        for (int c = 0; c < 4; c++) acc2[r][c] = 0ull;

#pragma unroll 2
    for (int d = 0; d < 128; d++) {
        const float* rowp = sXT + d * SXT_S;
        const u64* ap = (const u64*)(rowp + i0);
        ulonglong2 a01 = *(const ulonglong2*)(ap);
        ulonglong2 a23 = *(const ulonglong2*)(ap + 2);
        u64 a[4] = {a01.x, a01.y, a23.x, a23.y};
        float4 bj = *(const float4*)(rowp + j0);
        u64 bd[4];
        bd[0] = pack2(bj.x, bj.x); bd[1] = pack2(bj.y, bj.y);
        bd[2] = pack2(bj.z, bj.z); bd[3] = pack2(bj.w, bj.w);
#pragma unroll
        for (int r = 0; r < 4; r++)
#pragma unroll
            for (int c = 0; c < 4; c++) dfma(acc2[r][c], a[r], bd[c]);
    }

    // convert to packed radix keys IN REGISTERS: acc2[r][c] := (kh<<32)|kl
    {
        float sqj[4];
#pragma unroll
        for (int c = 0; c < 4; c++) sqj[c] = sSq[j0 + c];
#pragma unroll
        for (int r = 0; r < 4; r++) {
            int ia = i0 + 2 * r;
            float sqa = sSq[ia], sqb = sSq[ia + 1];
#pragma unroll
            for (int c = 0; c < 4; c++) {
                float lo, hi;
                unpack2(acc2[r][c], lo, hi);
                unsigned kl = fkey(sqa + sqj[c] - 2.0f * lo);
                unsigned kh = fkey(sqb + sqj[c] - 2.0f * hi);
                acc2[r][c] = ((u64)kh << 32) | (u64)kl;
            }
        }
    }

    cp_wait0();          // q tile in place (all threads' chunks after barrier)
    __syncthreads();

    // per row-pair: dual radix-threshold select + list build + aggregate
    const unsigned lmask = (1u << l) - 1u;

#pragma unroll 1
    for (int r = 0; r < 4; r++) {
        unsigned ka[2][4];
#pragma unroll
        for (int c = 0; c < 4; c++) {
            ka[0][c] = (unsigned)acc2[r][c];
            ka[1][c] = (unsigned)(acc2[r][c] >> 32);
        }

        unsigned lo0 = 0, hi0 = 0xffffffffu, lo1 = 0, hi1 = 0xffffffffu;
#pragma unroll 1
        for (int it = 0; it < 32; it++) {
            unsigned m0 = lo0 + ((hi0 - lo0) >> 1);
            unsigned m1 = lo1 + ((hi1 - lo1) >> 1);
            int c0 = (ka[0][0] <= m0) + (ka[0][1] <= m0) + (ka[0][2] <= m0) + (ka[0][3] <= m0);
            int c1 = (ka[1][0] <= m1) + (ka[1][1] <= m1) + (ka[1][2] <= m1) + (ka[1][3] <= m1);
            c0 = __reduce_add_sync(0xffffffffu, c0);
            c1 = __reduce_add_sync(0xffffffffu, c1);
            if (c0 >= KNN) hi0 = m0; else lo0 = m0 + 1;
            if (c1 >= KNN) hi1 = m1; else lo1 = m1 + 1;
        }
        const unsigned KV[2] = {lo0, lo1};

#pragma unroll 1
        for (int rr = 0; rr < 2; rr++) {
            const int i = i0 + 2 * r + rr;
            const unsigned kv = KV[rr];

            int cl = 0;
#pragma unroll
            for (int c = 0; c < 4; c++) cl += (ka[rr][c] < kv) ? 1 : 0;
            int c0tot = __reduce_add_sync(0xffffffffu, cl);
            int rem = KNN - c0tot;   // ties to take, ascending j = 4l+c

            bool eq[4], sel[4];
            unsigned bal[4];
#pragma unroll
            for (int c = 0; c < 4; c++) {
                eq[c] = (ka[rr][c] == kv);
                bal[c] = __ballot_sync(0xffffffffu, eq[c]);
            }
            int tiesLower = 0;
#pragma unroll
            for (int c = 0; c < 4; c++) tiesLower += __popc(bal[c] & lmask);
            int lp = 0;
#pragma unroll
            for (int c = 0; c < 4; c++) {
                sel[c] = (ka[rr][c] < kv) || (eq[c] && (tiesLower + lp) < rem);
                lp += eq[c] ? 1 : 0;
            }

            unsigned sbal[4];
#pragma unroll
            for (int c = 0; c < 4; c++) sbal[c] = __ballot_sync(0xffffffffu, sel[c]);
            int selLower = 0;
#pragma unroll
            for (int c = 0; c < 4; c++) selLower += __popc(sbal[c] & lmask);
            int sp = 0;
#pragma unroll
            for (int c = 0; c < 4; c++) {
                if (sel[c]) sList[i * KNN + selLower + sp] = j0 + c;
                sp += sel[c] ? 1 : 0;
            }
            __syncwarp();

            // aggregate: max of selected q rows, then elu(p + max)
            const int fo = 4 * l;
            float4 pv = *(const float4*)(PQg + (size_t)i * 256 + fo);
            float4 qm = make_float4(-3.0e38f, -3.0e38f, -3.0e38f, -3.0e38f);
#pragma unroll 4
            for (int it = 0; it < KNN; it++) {
                int j = sList[i * KNN + it];
                float4 qv = *(const float4*)(sQ + j * 128 + fo);
                qm.x = fmaxf(qm.x, qv.x);
                qm.y = fmaxf(qm.y, qv.y);
                qm.z = fmaxf(qm.z, qv.z);
                qm.w = fmaxf(qm.w, qv.w);
            }
            float4 ov;
            ov.x = elu_fast(pv.x + qm.x);
            ov.y = elu_fast(pv.y + qm.y);
            ov.z = elu_fast(pv.z + qm.z);
            ov.w = elu_fast(pv.w + qm.w);
            *(float4*)(OUT + ((size_t)g * NPG + i) * HID + fo) = ov;
        }
    }
}

// ---------------- sum-pool + output MLP -------------------------------------
__global__ __launch_bounds__(128) void pool_mlp(
    const float* __restrict__ X,
    const float* __restrict__ w1, const float* __restrict__ b1,
    const float* __restrict__ w2, const float* __restrict__ b2,
    const float* __restrict__ w3, const float* __restrict__ b3,
    const float* __restrict__ w4, const float* __restrict__ b4,
    float* __restrict__ out)
{
    __shared__ float pooled[128];
    __shared__ float o1[64];
    __shared__ float o2[32];
    __shared__ float o3[32];
    const int g = blockIdx.x, t = threadIdx.x;
    const float* Xg = X + (size_t)g * NPG * HID;

    float s = 0.0f;
    for (int n = 0; n < NPG; n++) s += Xg[n * HID + t];
    pooled[t] = s;
    __syncthreads();

    if (t < 64) {
        float a = b1[t];
        for (int d = 0; d < 128; d++) a += pooled[d] * w1[d * 64 + t];
        o1[t] = elu_fast(a);
    }
    __syncthreads();
    if (t < 32) {
        float a = b2[t];
        for (int d = 0; d < 64; d++) a += o1[d] * w2[d * 32 + t];
        o2[t] = elu_fast(a);
    }
    __syncthreads();
    if (t < 32) {
        float a = b3[t];
        for (int d = 0; d < 32; d++) a += o2[d] * w3[d * 32 + t];
        o3[t] = elu_fast(a);
    }
    __syncthreads();
    if (t < 6) {
        float a = b4[t];
        for (int d = 0; d < 32; d++) a += o3[d] * w4[d * 6 + t];
        out[g * 6 + t] = a;
    }
}

__global__ void copy_batch(const int* __restrict__ b, float* __restrict__ out)
{
    int i = blockIdx.x * 256 + threadIdx.x;
    if (i < NODES) out[i] = (float)b[i];
}

// ---------------------------------------------------------------------------
extern "C" void kernel_launch(void* const* d_in, const int* in_sizes, int n_in,
                              void* d_out, int out_size)
{
    const float* x_pf    = (const float*)d_in[0];
    const float* enc_w1  = (const float*)d_in[1];
    const float* enc_b1  = (const float*)d_in[2];
    const float* enc_w2  = (const float*)d_in[3];
    const float* enc_b2  = (const float*)d_in[4];
    const float* conv_w[3] = {(const float*)d_in[5], (const float*)d_in[7], (const float*)d_in[9]};
    const float* conv_b[3] = {(const float*)d_in[6], (const float*)d_in[8], (const float*)d_in[10]};
    const float* out_w1  = (const float*)d_in[11];
    const float* out_b1  = (const float*)d_in[12];
    const float* out_w2  = (const float*)d_in[13];
    const float* out_b2  = (const float*)d_in[14];
    const float* out_w3  = (const float*)d_in[15];
    const float* out_b3  = (const float*)d_in[16];
    const float* out_w4  = (const float*)d_in[17];
    const float* out_b4  = (const float*)d_in[18];
    const int*   batch   = (const int*)d_in[19];

    float *featA, *featB, *pq, *wc3;
    cudaGetSymbolAddress((void**)&featA, g_feat_a);
    cudaGetSymbolAddress((void**)&featB, g_feat_b);
    cudaGetSymbolAddress((void**)&pq,    g_pq);
    cudaGetSymbolAddress((void**)&wc3,   g_wc3);

    cudaFuncSetAttribute(mm_kernel, cudaFuncAttributeMaxDynamicSharedMemorySize, MM_SMEM);
    cudaFuncSetAttribute(knn_agg,   cudaFuncAttributeMaxDynamicSharedMemorySize, SMEM_KNN);

    // weight concat for all 3 convs upfront
    for (int c = 0; c < 3; c++)
        build_wcat<<<128, 256>>>(conv_w[c], wc3 + c * HID * 2 * HID);

    // encoder
    mm_kernel<<<dim3(NODES / 128, 1), 256, MM_SMEM>>>(x_pf,  enc_w1, enc_b1, 128, 1, featB, 128, 16);
    mm_kernel<<<dim3(NODES / 128, 1), 256, MM_SMEM>>>(featB, enc_w2, enc_b2, 128, 1, featA, 128, 128);

    // 3 dynamic edge convs
    float* cur = featA;
    float* nxt = featB;
    for (int cidx = 0; cidx < 3; cidx++) {
        mm_kernel<<<dim3(NODES / 128, 2), 256, MM_SMEM>>>(cur, wc3 + cidx * HID * 2 * HID,
                                                          conv_b[cidx], 128, 0, pq, 2 * HID, HID);
        knn_agg<<<NG, 512, SMEM_KNN>>>(cur, pq, nxt);
        float* t = cur; cur = nxt; nxt = t;
    }

    pool_mlp<<<NG, 128>>>(cur, out_w1, out_b1, out_w2, out_b2,
                          out_w3, out_b3, out_w4, out_b4, (float*)d_out);

    copy_batch<<<(NODES + 255) / 256, 256>>>(batch, (float*)d_out + NG * 6);
}

// round 10
// speedup vs baseline: 1.3436x; 1.0047x over previous
#include <cuda_runtime.h>
#include <cstdint>

#define NODES   16384
#define NPG     128
#define NG      128
#define HID     128
#define KNN     24
#define SXT_S   132

typedef unsigned long long u64;

// ---------------- scratch ----------------
__device__ float g_feat_a[NODES * HID];
__device__ float g_feat_b[NODES * HID];
__device__ float g_pq[NODES * 2 * HID];
__device__ float g_wc3[3 * HID * 2 * HID];

__device__ __forceinline__ float elu_fast(float v) {
    return v > 0.0f ? v : (__expf(v) - 1.0f);
}

__device__ __forceinline__ unsigned fkey(float v) {
    unsigned b = __float_as_uint(v);
    return b ^ ((b & 0x80000000u) ? 0xffffffffu : 0x80000000u);
}

// ---- packed fp32x2 helpers (sm_103a FFMA2) ----
__device__ __forceinline__ u64 pack2(float lo, float hi) {
    u64 r; asm("mov.b64 %0,{%1,%2};" : "=l"(r) : "f"(lo), "f"(hi)); return r;
}
__device__ __forceinline__ void unpack2(u64 v, float& lo, float& hi) {
    asm("mov.b64 {%0,%1},%2;" : "=f"(lo), "=f"(hi) : "l"(v));
}
__device__ __forceinline__ void dfma(u64& d, u64 a, u64 b) {
    asm("fma.rn.f32x2 %0,%1,%2,%0;" : "+l"(d) : "l"(a), "l"(b));
}

// ---- cp.async helpers ----
__device__ __forceinline__ void cp16(void* smem, const void* gmem) {
    unsigned s = (unsigned)__cvta_generic_to_shared(smem);
    asm volatile("cp.async.cg.shared.global [%0], [%1], 16;\n" :: "r"(s), "l"(gmem));
}
__device__ __forceinline__ void cp_commit() { asm volatile("cp.async.commit_group;\n"); }
__device__ __forceinline__ void cp_wait0()  { asm volatile("cp.async.wait_group 0;\n"); }

// ---------------- pipelined 128x128-tile fp32 matmul (FFMA2) ---------------
// (R5 code, verified)
__global__ __launch_bounds__(256, 2) void mm_kernel(
    const float* __restrict__ A, const float* __restrict__ B,
    const float* __restrict__ bias, int biasLimit, int doElu,
    float* __restrict__ C, int N, int K)
{
    extern __shared__ float smf[];
    float* As = smf;                   // [2][16*132]
    float* Bs = smf + 2 * 16 * 132;    // [2][16*128]

    const int tid = threadIdx.x;
    const int tx = tid & 15;
    const int ty = tid >> 4;
    const int rowBase = blockIdx.x * 128;
    const int colBase = blockIdx.y * 128;

    u64 acc2[4][8];
#pragma unroll
    for (int r = 0; r < 4; r++)
#pragma unroll
        for (int c = 0; c < 8; c++) acc2[r][c] = 0ull;

    int am[8], ak[8];
#pragma unroll
    for (int t = 0; t < 8; t++) {
        int idx = t * 256 + tid;
        am[t] = idx >> 4; ak[t] = idx & 15;
    }
    int bk[2], bn[2];
#pragma unroll
    for (int t = 0; t < 2; t++) {
        int idx = t * 256 + tid;
        bk[t] = idx >> 5;
        bn[t] = (idx & 31) * 4;
    }

    float aReg[8];
#pragma unroll
    for (int t = 0; t < 8; t++)
        aReg[t] = A[(size_t)(rowBase + am[t]) * K + ak[t]];
#pragma unroll
    for (int t = 0; t < 2; t++)
        cp16(&Bs[bk[t] * 128 + bn[t]], &B[(size_t)bk[t] * N + colBase + bn[t]]);
    cp_commit();
#pragma unroll
    for (int t = 0; t < 8; t++)
        As[ak[t] * 132 + am[t]] = aReg[t];
    cp_wait0();
    __syncthreads();

    int buf = 0;
    for (int kk = 0; kk < K; kk += 16) {
        const int nkk = kk + 16;
        if (nkk < K) {
#pragma unroll
            for (int t = 0; t < 8; t++)
                aReg[t] = A[(size_t)(rowBase + am[t]) * K + nkk + ak[t]];
#pragma unroll
            for (int t = 0; t < 2; t++)
                cp16(&Bs[(buf ^ 1) * 2048 + bk[t] * 128 + bn[t]],
                     &B[(size_t)(nkk + bk[t]) * N + colBase + bn[t]]);
            cp_commit();
        }

        const float* Asb = As + buf * 2112;
        const float* Bsb = Bs + buf * 2048;
#pragma unroll
        for (int k = 0; k < 16; k++) {
            const float* ap = &Asb[k * 132 + ty * 8];
            ulonglong2 t0 = *(const ulonglong2*)(ap);
            ulonglong2 t1 = *(const ulonglong2*)(ap + 4);
            u64 a[4] = {t0.x, t0.y, t1.x, t1.y};
            float4 b0 = *(const float4*)&Bsb[k * 128 + tx * 8];
            float4 b1 = *(const float4*)&Bsb[k * 128 + tx * 8 + 4];
            u64 bd[8];
            bd[0] = pack2(b0.x, b0.x); bd[1] = pack2(b0.y, b0.y);
            bd[2] = pack2(b0.z, b0.z); bd[3] = pack2(b0.w, b0.w);
            bd[4] = pack2(b1.x, b1.x); bd[5] = pack2(b1.y, b1.y);
            bd[6] = pack2(b1.z, b1.z); bd[7] = pack2(b1.w, b1.w);
#pragma unroll
            for (int r = 0; r < 4; r++)
#pragma unroll
                for (int c = 0; c < 8; c++) dfma(acc2[r][c], a[r], bd[c]);
        }

        if (nkk < K) {
#pragma unroll
            for (int t = 0; t < 8; t++)
                As[(buf ^ 1) * 2112 + ak[t] * 132 + am[t]] = aReg[t];
            cp_wait0();
            __syncthreads();
            buf ^= 1;
        }
    }

#pragma unroll
    for (int r = 0; r < 4; r++) {
        int row0 = rowBase + ty * 8 + 2 * r;
        float lo[8], hi[8];
#pragma unroll
        for (int c = 0; c < 8; c++) unpack2(acc2[r][c], lo[c], hi[c]);
#pragma unroll
        for (int c = 0; c < 8; c++) {
            int col = colBase + tx * 8 + c;
            if (col < biasLimit) { float bb = bias[col]; lo[c] += bb; hi[c] += bb; }
            if (doElu) { lo[c] = elu_fast(lo[c]); hi[c] = elu_fast(hi[c]); }
        }
        float* p0 = C + (size_t)row0 * N + colBase + tx * 8;
        float* p1 = p0 + N;
        *(float4*)p0       = make_float4(lo[0], lo[1], lo[2], lo[3]);
        *(float4*)(p0 + 4) = make_float4(lo[4], lo[5], lo[6], lo[7]);
        *(float4*)p1       = make_float4(hi[0], hi[1], hi[2], hi[3]);
        *(float4*)(p1 + 4) = make_float4(hi[4], hi[5], hi[6], hi[7]);
    }
}

#define MM_SMEM ((2*16*132 + 2*16*128) * 4)

// ---------------- build [Wa-Wb | Wb] ---------------------------------------
__global__ void build_wcat(const float* __restrict__ w, float* __restrict__ wc)
{
    int idx = blockIdx.x * 256 + threadIdx.x;
    int d = idx >> 8;
    int n = idx & 255;
    float v;
    if (n < 128) v = w[d * 128 + n] - w[(128 + d) * 128 + n];
    else         v = w[(128 + d) * 128 + (n - 128)];
    wc[idx] = v;
}

// ---------------- per-HALF-graph kNN + select + aggregate ------------------
// grid = 2*NG CTAs; CTA (g,h) computes output rows h*64..h*64+63 of graph g.
// sQ is ALIASED onto sXT (X dead after Gram) -> 72.5 KB smem -> 2-3 CTAs/SM.
#define KNN_R0   16896                   /* floats in region0 = max(sXT,sQ) */
#define SMEM_KNN ((KNN_R0 + 128) * 4 + 64 * KNN * 4)

__global__ __launch_bounds__(512) void knn_agg(
    const float* __restrict__ X, const float* __restrict__ PQ,
    float* __restrict__ OUT)
{
    extern __shared__ float sm[];
    float* sXT = sm;                          // [f][n] stride 132 (phases 1-3)
    float* sQ  = sm;                          // [n][f] 128x128    (phase 6) ALIAS
    float* sSq = sm + KNN_R0;                 // [n]
    int*   sList = (int*)(sSq + 128);         // [iloc][24], iloc 0..63

    const int g   = blockIdx.x >> 1;
    const int h   = blockIdx.x & 1;
    const int tid = threadIdx.x;
    const float* Xg  = X  + (size_t)g * NPG * HID;
    const float* PQg = PQ + (size_t)g * NPG * 2 * HID;

    // phase 1: load X (transposed)
    for (int idx = tid; idx < NPG * HID; idx += 512) {
        int n = idx >> 7, f = idx & 127;
        sXT[f * SXT_S + n] = Xg[idx];
    }
    __syncthreads();

    // phase 2: squared norms (all 128, needed as column terms)
    if (tid < 128) {
        float s = 0.0f;
#pragma unroll 8
        for (int d = 0; d < 128; d++) {
            float v = sXT[d * SXT_S + tid];
            s += v * v;
        }
        sSq[tid] = s;
    }
    __syncthreads();

    // phase 3: Gram for this half. Warp w owns rows i0..i0+3, lane l owns
    // cols 4l..4l+3. acc2[r][c] = f32x2 over row-pair (i0+2r, i0+2r+1).
    const int w = tid >> 5;
    const int l = tid & 31;
    const int i0 = h * 64 + w * 4;    // global row in graph
    const int j0 = l * 4;

    u64 acc2[2][4];
#pragma unroll
    for (int r = 0; r < 2; r++)
#pragma unroll
        for (int c = 0; c < 4; c++) acc2[r][c] = 0ull;

#pragma unroll 4
    for (int d = 0; d < 128; d++) {
        const float* rowp = sXT + d * SXT_S;
        ulonglong2 a01 = *(const ulonglong2*)(rowp + i0);
        u64 a[2] = {a01.x, a01.y};
        float4 bj = *(const float4*)(rowp + j0);
        u64 bd[4];
        bd[0] = pack2(bj.x, bj.x); bd[1] = pack2(bj.y, bj.y);
        bd[2] = pack2(bj.z, bj.z); bd[3] = pack2(bj.w, bj.w);
#pragma unroll
        for (int r = 0; r < 2; r++)
#pragma unroll
            for (int c = 0; c < 4; c++) dfma(acc2[r][c], a[r], bd[c]);
    }
    __syncthreads();     // all sXT reads complete — region0 may be reused

    // phase 4: stream q tile into the aliased region (overlaps select)
#pragma unroll
    for (int t = 0; t < 8; t++) {
        int idx = t * 512 + tid;
        int n = idx >> 5, c4 = (idx & 31) * 4;
        cp16(&sQ[n * 128 + c4], &PQg[n * 256 + 128 + c4]);
    }
    cp_commit();

    // phase 5: keys (registers) + dual radix-threshold select + list build
    {
        float sqj[4];
#pragma unroll
        for (int c = 0; c < 4; c++) sqj[c] = sSq[j0 + c];
#pragma unroll
        for (int r = 0; r < 2; r++) {
            int ia = i0 + 2 * r;
            float sqa = sSq[ia], sqb = sSq[ia + 1];
#pragma unroll
            for (int c = 0; c < 4; c++) {
                float lo, hi;
                unpack2(acc2[r][c], lo, hi);
                unsigned kl = fkey(sqa + sqj[c] - 2.0f * lo);
                unsigned kh = fkey(sqb + sqj[c] - 2.0f * hi);
                acc2[r][c] = ((u64)kh << 32) | (u64)kl;
            }
        }
    }

    const unsigned lmask = (1u << l) - 1u;

#pragma unroll 1
    for (int r = 0; r < 2; r++) {
        unsigned ka[2][4];
#pragma unroll
        for (int c = 0; c < 4; c++) {
            ka[0][c] = (unsigned)acc2[r][c];
            ka[1][c] = (unsigned)(acc2[r][c] >> 32);
        }

        unsigned lo0 = 0, hi0 = 0xffffffffu, lo1 = 0, hi1 = 0xffffffffu;
#pragma unroll 1
        for (int it = 0; it < 32; it++) {
            unsigned m0 = lo0 + ((hi0 - lo0) >> 1);
            unsigned m1 = lo1 + ((hi1 - lo1) >> 1);
            int c0 = (ka[0][0] <= m0) + (ka[0][1] <= m0) + (ka[0][2] <= m0) + (ka[0][3] <= m0);
            int c1 = (ka[1][0] <= m1) + (ka[1][1] <= m1) + (ka[1][2] <= m1) + (ka[1][3] <= m1);
            c0 = __reduce_add_sync(0xffffffffu, c0);
            c1 = __reduce_add_sync(0xffffffffu, c1);
            if (c0 >= KNN) hi0 = m0; else lo0 = m0 + 1;
            if (c1 >= KNN) hi1 = m1; else lo1 = m1 + 1;
        }
        const unsigned KV[2] = {lo0, lo1};

#pragma unroll 1
        for (int rr = 0; rr < 2; rr++) {
            const int iloc = w * 4 + 2 * r + rr;     // 0..63
            const unsigned kv = KV[rr];

            int cl = 0;
#pragma unroll
            for (int c = 0; c < 4; c++) cl += (ka[rr][c] < kv) ? 1 : 0;
            int c0tot = __reduce_add_sync(0xffffffffu, cl);
            int rem = KNN - c0tot;   // ties to take, ascending j = 4l+c

            bool eq[4], sel[4];
            unsigned bal[4];
#pragma unroll
            for (int c = 0; c < 4; c++) {
                eq[c] = (ka[rr][c] == kv);
                bal[c] = __ballot_sync(0xffffffffu, eq[c]);
            }
            int tiesLower = 0;
#pragma unroll
            for (int c = 0; c < 4; c++) tiesLower += __popc(bal[c] & lmask);
            int lp = 0;
#pragma unroll
            for (int c = 0; c < 4; c++) {
                sel[c] = (ka[rr][c] < kv) || (eq[c] && (tiesLower + lp) < rem);
                lp += eq[c] ? 1 : 0;
            }

            unsigned sbal[4];
#pragma unroll
            for (int c = 0; c < 4; c++) sbal[c] = __ballot_sync(0xffffffffu, sel[c]);
            int selLower = 0;
#pragma unroll
            for (int c = 0; c < 4; c++) selLower += __popc(sbal[c] & lmask);
            int sp = 0;
#pragma unroll
            for (int c = 0; c < 4; c++) {
                if (sel[c]) sList[iloc * KNN + selLower + sp] = j0 + c;
                sp += sel[c] ? 1 : 0;
            }
        }
    }

    cp_wait0();
    __syncthreads();     // q tile in place, lists complete

    // phase 6: aggregate: max of selected q rows, then elu(p + max)
    const int fo = 4 * l;
#pragma unroll 1
    for (int rr = 0; rr < 4; rr++) {
        const int iloc = w * 4 + rr;
        const int i = h * 64 + iloc;
        float4 pv = *(const float4*)(PQg + (size_t)i * 256 + fo);
        float4 qm = make_float4(-3.0e38f, -3.0e38f, -3.0e38f, -3.0e38f);
#pragma unroll 4
        for (int it = 0; it < KNN; it++) {
            int j = sList[iloc * KNN + it];
            float4 qv = *(const float4*)(sQ + j * 128 + fo);
            qm.x = fmaxf(qm.x, qv.x);
            qm.y = fmaxf(qm.y, qv.y);
            qm.z = fmaxf(qm.z, qv.z);
            qm.w = fmaxf(qm.w, qv.w);
        }
        float4 ov;
        ov.x = elu_fast(pv.x + qm.x);
        ov.y = elu_fast(pv.y + qm.y);
        ov.z = elu_fast(pv.z + qm.z);
        ov.w = elu_fast(pv.w + qm.w);
        *(float4*)(OUT + ((size_t)g * NPG + i) * HID + fo) = ov;
    }
}

// ---------------- sum-pool + output MLP -------------------------------------
__global__ __launch_bounds__(128) void pool_mlp(
    const float* __restrict__ X,
    const float* __restrict__ w1, const float* __restrict__ b1,
    const float* __restrict__ w2, const float* __restrict__ b2,
    const float* __restrict__ w3, const float* __restrict__ b3,
    const float* __restrict__ w4, const float* __restrict__ b4,
    float* __restrict__ out)
{
    __shared__ float pooled[128];
    __shared__ float o1[64];
    __shared__ float o2[32];
    __shared__ float o3[32];
    const int g = blockIdx.x, t = threadIdx.x;
    const float* Xg = X + (size_t)g * NPG * HID;

    float s = 0.0f;
    for (int n = 0; n < NPG; n++) s += Xg[n * HID + t];
    pooled[t] = s;
    __syncthreads();

    if (t < 64) {
        float a = b1[t];
        for (int d = 0; d < 128; d++) a += pooled[d] * w1[d * 64 + t];
        o1[t] = elu_fast(a);
    }
    __syncthreads();
    if (t < 32) {
        float a = b2[t];
        for (int d = 0; d < 64; d++) a += o1[d] * w2[d * 32 + t];
        o2[t] = elu_fast(a);
    }
    __syncthreads();
    if (t < 32) {
        float a = b3[t];
        for (int d = 0; d < 32; d++) a += o2[d] * w3[d * 32 + t];
        o3[t] = elu_fast(a);
    }
    __syncthreads();
    if (t < 6) {
        float a = b4[t];
        for (int d = 0; d < 32; d++) a += o3[d] * w4[d * 6 + t];
        out[g * 6 + t] = a;
    }
}

__global__ void copy_batch(const int* __restrict__ b, float* __restrict__ out)
{
    int i = blockIdx.x * 256 + threadIdx.x;
    if (i < NODES) out[i] = (float)b[i];
}

// ---------------------------------------------------------------------------
extern "C" void kernel_launch(void* const* d_in, const int* in_sizes, int n_in,
                              void* d_out, int out_size)
{
    const float* x_pf    = (const float*)d_in[0];
    const float* enc_w1  = (const float*)d_in[1];
    const float* enc_b1  = (const float*)d_in[2];
    const float* enc_w2  = (const float*)d_in[3];
    const float* enc_b2  = (const float*)d_in[4];
    const float* conv_w[3] = {(const float*)d_in[5], (const float*)d_in[7], (const float*)d_in[9]};
    const float* conv_b[3] = {(const float*)d_in[6], (const float*)d_in[8], (const float*)d_in[10]};
    const float* out_w1  = (const float*)d_in[11];
    const float* out_b1  = (const float*)d_in[12];
    const float* out_w2  = (const float*)d_in[13];
    const float* out_b2  = (const float*)d_in[14];
    const float* out_w3  = (const float*)d_in[15];
    const float* out_b3  = (const float*)d_in[16];
    const float* out_w4  = (const float*)d_in[17];
    const float* out_b4  = (const float*)d_in[18];
    const int*   batch   = (const int*)d_in[19];

    float *featA, *featB, *pq, *wc3;
    cudaGetSymbolAddress((void**)&featA, g_feat_a);
    cudaGetSymbolAddress((void**)&featB, g_feat_b);
    cudaGetSymbolAddress((void**)&pq,    g_pq);
    cudaGetSymbolAddress((void**)&wc3,   g_wc3);

    cudaFuncSetAttribute(mm_kernel, cudaFuncAttributeMaxDynamicSharedMemorySize, MM_SMEM);
    cudaFuncSetAttribute(knn_agg,   cudaFuncAttributeMaxDynamicSharedMemorySize, SMEM_KNN);

    // weight concat for all 3 convs upfront
    for (int c = 0; c < 3; c++)
        build_wcat<<<128, 256>>>(conv_w[c], wc3 + c * HID * 2 * HID);

    // encoder
    mm_kernel<<<dim3(NODES / 128, 1), 256, MM_SMEM>>>(x_pf,  enc_w1, enc_b1, 128, 1, featB, 128, 16);
    mm_kernel<<<dim3(NODES / 128, 1), 256, MM_SMEM>>>(featB, enc_w2, enc_b2, 128, 1, featA, 128, 128);

    // 3 dynamic edge convs
    float* cur = featA;
    float* nxt = featB;
    for (int cidx = 0; cidx < 3; cidx++) {
        mm_kernel<<<dim3(NODES / 128, 2), 256, MM_SMEM>>>(cur, wc3 + cidx * HID * 2 * HID,
                                                          conv_b[cidx], 128, 0, pq, 2 * HID, HID);
        knn_agg<<<2 * NG, 512, SMEM_KNN>>>(cur, pq, nxt);
        float* t = cur; cur = nxt; nxt = t;
    }

    pool_mlp<<<NG, 128>>>(cur, out_w1, out_b1, out_w2, out_b2,
                          out_w3, out_b3, out_w4, out_b4, (float*)d_out);

    copy_batch<<<(NODES + 255) / 256, 256>>>(batch, (float*)d_out + NG * 6);
}